// round 2
// baseline (speedup 1.0000x reference)
#include <cuda_runtime.h>
#include <math.h>

// Problem dims
#define B   512
#define T   512
#define L   64
#define H   512
#define G3  1536          // 3*H
#define XW  575           // T + L - 1

// GEMM tile
#define BM 64
#define BN 64
#define BK 16

// -------- device scratch (static: no allocation allowed) --------
__device__ float g_GI1[(size_t)L * B * G3];   // precomputed x-side gates, layer 1: [L][B][3H]
__device__ float g_GH1[(size_t)B * G3];       // per-step h-side gates, layer 1
__device__ float g_GI2[(size_t)B * G3];       // per-step x-side gates, layer 2
__device__ float g_GH2[(size_t)B * G3];       // per-step h-side gates, layer 2
__device__ float g_h1 [(size_t)B * H];        // running hidden, layer 1
__device__ float g_h2 [(size_t)B * H];        // running hidden, layer 2
__device__ float g_H2A[(size_t)L * B * H];    // h2 history for the FC head: [L][B][H]

// ---------------------------------------------------------------
// C[M,N] tile = A[M,K] @ W[N,K]^T + bias[N]
// A row-major with runtime lda (supports the sliding-window view of x),
// W row-major [N,K] (so both operands stream contiguously along K).
// 64x64 block tile, BK=16, 256 threads, 4x4 per-thread micro-tile.
// M, N multiples of 64; K multiple of 16 (all true here: K=512 always).
// ---------------------------------------------------------------
__device__ __forceinline__ void gemm_tile(
    const float* __restrict__ A, int lda,
    const float* __restrict__ W, int K,
    const float* __restrict__ bias,
    float* __restrict__ C, int ldc)
{
    __shared__ float As[BK][BM];
    __shared__ float Bs[BK][BN];

    const int tid = threadIdx.x;
    const int tx = tid & 15;
    const int ty = tid >> 4;
    const int m0 = blockIdx.y * BM;
    const int n0 = blockIdx.x * BN;

    const int arow = tid >> 2;         // 0..63
    const int ac4  = (tid & 3) << 2;   // 0,4,8,12

    const float* Ap = A + (size_t)(m0 + arow) * lda;
    const float* Wp = W + (size_t)(n0 + arow) * K;

    float acc[4][4] = {};

    for (int k0 = 0; k0 < K; k0 += BK) {
        // A tile: scalar loads (x-window base pointer is not 16B aligned)
        #pragma unroll
        for (int i = 0; i < 4; i++)
            As[ac4 + i][arow] = Ap[k0 + ac4 + i];
        // W tile: rows are K=512 floats, 16B aligned -> float4
        float4 w = *reinterpret_cast<const float4*>(Wp + k0 + ac4);
        Bs[ac4 + 0][arow] = w.x;
        Bs[ac4 + 1][arow] = w.y;
        Bs[ac4 + 2][arow] = w.z;
        Bs[ac4 + 3][arow] = w.w;
        __syncthreads();

        #pragma unroll
        for (int kk = 0; kk < BK; kk++) {
            float a[4], b[4];
            #pragma unroll
            for (int i = 0; i < 4; i++) a[i] = As[kk][ty * 4 + i];
            #pragma unroll
            for (int j = 0; j < 4; j++) b[j] = Bs[kk][tx * 4 + j];
            #pragma unroll
            for (int i = 0; i < 4; i++)
                #pragma unroll
                for (int j = 0; j < 4; j++)
                    acc[i][j] = fmaf(a[i], b[j], acc[i][j]);
        }
        __syncthreads();
    }

    #pragma unroll
    for (int i = 0; i < 4; i++) {
        const int m = m0 + ty * 4 + i;
        #pragma unroll
        for (int j = 0; j < 4; j++) {
            const int n = n0 + tx * 4 + j;
            C[(size_t)m * ldc + n] = acc[i][j] + bias[n];
        }
    }
}

// ---- GEMM wrappers ----

// Precompute all x-side gates of layer 1 for every step in one launch.
// grid.z = t; A is the window x[:, t:t+T] i.e. base x + t with lda = XW.
__global__ void k_gi1(const float* __restrict__ x,
                      const float* __restrict__ Wih1,
                      const float* __restrict__ bih1)
{
    const int t = blockIdx.z;
    gemm_tile(x + t, XW, Wih1, T, bih1, g_GI1 + (size_t)t * B * G3, G3);
}

// Layer-1 hidden-side gates: GH1 = h1 @ W_hh1^T + b_hh1
__global__ void k_gh1(const float* __restrict__ Whh1,
                      const float* __restrict__ bhh1)
{
    gemm_tile(g_h1, H, Whh1, H, bhh1, g_GH1, G3);
}

// Layer-2 gates (two independent GEMMs packed on grid.z):
//   z=0: GI2 = h1 @ W_ih2^T + b_ih2     z=1: GH2 = h2 @ W_hh2^T + b_hh2
__global__ void k_g2(const float* __restrict__ Wih2, const float* __restrict__ bih2,
                     const float* __restrict__ Whh2, const float* __restrict__ bhh2)
{
    if (blockIdx.z == 0)
        gemm_tile(g_h1, H, Wih2, H, bih2, g_GI2, G3);
    else
        gemm_tile(g_h2, H, Whh2, H, bhh2, g_GH2, G3);
}

// ---- pointwise GRU gate updates ----

__device__ __forceinline__ float sigmoidf_(float v) { return 1.0f / (1.0f + expf(-v)); }

__global__ void k_gate1(int t)
{
    const int idx = blockIdx.x * blockDim.x + threadIdx.x;   // < B*H
    const int b = idx >> 9;
    const int j = idx & (H - 1);
    const float* gi = g_GI1 + (size_t)t * B * G3 + (size_t)b * G3;
    const float* gh = g_GH1 + (size_t)b * G3;
    const float r = sigmoidf_(gi[j]         + gh[j]);
    const float z = sigmoidf_(gi[H + j]     + gh[H + j]);
    const float n = tanhf    (gi[2 * H + j] + r * gh[2 * H + j]);
    const float h = g_h1[idx];
    g_h1[idx] = (1.0f - z) * n + z * h;
}

__global__ void k_gate2(int t)
{
    const int idx = blockIdx.x * blockDim.x + threadIdx.x;   // < B*H
    const int b = idx >> 9;
    const int j = idx & (H - 1);
    const float* gi = g_GI2 + (size_t)b * G3;
    const float* gh = g_GH2 + (size_t)b * G3;
    const float r = sigmoidf_(gi[j]         + gh[j]);
    const float z = sigmoidf_(gi[H + j]     + gh[H + j]);
    const float n = tanhf    (gi[2 * H + j] + r * gh[2 * H + j]);
    const float h = g_h2[idx];
    const float hn = (1.0f - z) * n + z * h;
    g_h2[idx] = hn;
    g_H2A[(size_t)t * B * H + idx] = hn;     // log for the FC head
}

// ---- FC head over the whole h2 history: out[b*L + t] = h2_t[b,:] . W_fc + b_fc ----
__global__ void k_y(const float* __restrict__ Wfc, const float* __restrict__ bfc,
                    float* __restrict__ out)
{
    const int w    = (blockIdx.x * blockDim.x + threadIdx.x) >> 5;  // warp id = (b, t)
    const int lane = threadIdx.x & 31;
    const int b = w >> 6;       // / L
    const int t = w & (L - 1);
    const float* h2 = g_H2A + ((size_t)t * B + b) * H;
    float acc = 0.0f;
    #pragma unroll 4
    for (int j = lane; j < H; j += 32) acc += h2[j] * Wfc[j];
    #pragma unroll
    for (int o = 16; o; o >>= 1) acc += __shfl_xor_sync(0xffffffffu, acc, o);
    if (lane == 0) out[b * L + t] = acc + bfc[0];
}

// ---- init / finalize ----
__global__ void k_init(const float* __restrict__ h1i, const float* __restrict__ h2i)
{
    const int i = blockIdx.x * blockDim.x + threadIdx.x;
    g_h1[i] = h1i[i];
    g_h2[i] = h2i[i];
}

__global__ void k_fin(float* __restrict__ out)
{
    const int i = blockIdx.x * blockDim.x + threadIdx.x;
    out[B * L + i]         = g_h1[i];
    out[B * L + B * H + i] = g_h2[i];
}

// ---------------------------------------------------------------
extern "C" void kernel_launch(void* const* d_in, const int* in_sizes, int n_in,
                              void* d_out, int out_size)
{
    (void)in_sizes; (void)n_in; (void)out_size;
    const float* x    = (const float*)d_in[0];
    const float* h1i  = (const float*)d_in[1];
    const float* h2i  = (const float*)d_in[2];
    const float* Wih1 = (const float*)d_in[3];
    const float* Whh1 = (const float*)d_in[4];
    const float* bih1 = (const float*)d_in[5];
    const float* bhh1 = (const float*)d_in[6];
    const float* Wih2 = (const float*)d_in[7];
    const float* Whh2 = (const float*)d_in[8];
    const float* bih2 = (const float*)d_in[9];
    const float* bhh2 = (const float*)d_in[10];
    const float* Wfc  = (const float*)d_in[11];
    const float* bfc  = (const float*)d_in[12];
    float* out = (float*)d_out;

    k_init<<<(B * H) / 256, 256>>>(h1i, h2i);

    // Hoisted input-side GEMM for all L steps (no recurrent dependency).
    dim3 gpre(G3 / BN, B / BM, L);
    k_gi1<<<gpre, 256>>>(x, Wih1, bih1);

    dim3 gone(G3 / BN, B / BM, 1);
    dim3 gtwo(G3 / BN, B / BM, 2);
    for (int t = 0; t < L; t++) {
        k_gh1 <<<gone, 256>>>(Whh1, bhh1);
        k_gate1<<<(B * H) / 256, 256>>>(t);
        k_g2  <<<gtwo, 256>>>(Wih2, bih2, Whh2, bhh2);
        k_gate2<<<(B * H) / 256, 256>>>(t);
    }

    k_y  <<<(B * L * 32) / 256, 256>>>(Wfc, bfc, out);
    k_fin<<<(B * H) / 256, 256>>>(out);
}

// round 7
// speedup vs baseline: 2.0259x; 2.0259x over previous
#include <cuda_runtime.h>
#include <cuda_bf16.h>
#include <math.h>
#include <stdint.h>

// Problem dims
#define B   512
#define T   512
#define L   64
#define H   512
#define G3  1536
#define XW  575
#define K512 512
#define BK   32
#define NIT  16           // K512 / BK
#define TM   64
#define TN   128
// smem (single buffer): A_hi 64*80, A_lo 64*80, B_hi 128*80, B_lo 128*80
#define ROWB 80
#define OFF_AHI 0
#define OFF_ALO 5120
#define OFF_BHI 10240
#define OFF_BLO 20480
#define SMEM_DYN 30720

// -------- device scratch: EXACTLY the round-2 (passing) set --------
__device__ float g_GI1[(size_t)L * B * G3];
__device__ float g_GH1[(size_t)B * G3];
__device__ float g_GI2[(size_t)B * G3];
__device__ float g_GH2[(size_t)B * G3];
__device__ float g_h1 [(size_t)B * H];
__device__ float g_h2 [(size_t)B * H];
__device__ float g_H2A[(size_t)L * B * H];

// ---------------- PTX helpers ----------------
__device__ __forceinline__ void mma16816(float* d, const uint32_t* a, const uint32_t* b) {
    asm volatile(
        "mma.sync.aligned.m16n8k16.row.col.f32.bf16.bf16.f32 "
        "{%0,%1,%2,%3}, {%4,%5,%6,%7}, {%8,%9}, {%0,%1,%2,%3};"
        : "+f"(d[0]), "+f"(d[1]), "+f"(d[2]), "+f"(d[3])
        : "r"(a[0]), "r"(a[1]), "r"(a[2]), "r"(a[3]), "r"(b[0]), "r"(b[1]));
}

// ---------------------------------------------------------------
// C[TM,TN] tile = A[TM,K512] @ W[TN-row slice, K512]^T + bias
// fp32 operands are split to (hi,lo) bf16 in smem each K-chunk; the
// compensated product hi*hi + lo*hi + hi*lo restores ~fp32 accuracy.
// mma fragments via explicit per-lane LDS from padded smem (80B rows,
// conflict-free). Plain LDG->STS (no cp.async). 256 threads.
// ---------------------------------------------------------------
__device__ void gemm_core(const float* __restrict__ A, int lda,
                          const float* __restrict__ W,
                          const float* __restrict__ bias,
                          float* __restrict__ C)
{
    extern __shared__ __align__(128) char sm[];
    const int tid  = threadIdx.x;
    const int wid  = tid >> 5;
    const int lane = tid & 31;
    const int m0 = blockIdx.y * TM;
    const int n0 = blockIdx.x * TN;

    const int arow = tid >> 2;          // 0..63
    const int ac8  = (tid & 3) * 8;     // element group of 8 within BK=32

    const int wm = (wid & 1) * 32;      // warp m offset (2 warps over 64)
    const int wn = (wid >> 1) * 32;     // warp n offset (4 warps over 128)
    const int r8 = lane >> 2;           // fragment row / n index 0..7
    const int c2 = (lane & 3) * 2;      // fragment k pair base

    float acc[2][4][4] = {};

    for (int it = 0; it < NIT; it++) {
        const int k = it * BK;

        // ---- load + split A rows (1 x 8 floats per thread) ----
        {
            const float* ap = A + (size_t)(m0 + arow) * lda + k + ac8;
            __align__(16) __nv_bfloat16 hi[8], lo[8];
            #pragma unroll
            for (int i = 0; i < 8; i++) {
                const float v = ap[i];
                hi[i] = __float2bfloat16(v);
                lo[i] = __float2bfloat16(v - __bfloat162float(hi[i]));
            }
            *(uint4*)(sm + OFF_AHI + arow * ROWB + ac8 * 2) = *(const uint4*)hi;
            *(uint4*)(sm + OFF_ALO + arow * ROWB + ac8 * 2) = *(const uint4*)lo;
        }
        // ---- load + split W rows (2 x 8 floats per thread) ----
        #pragma unroll
        for (int p = 0; p < 2; p++) {
            const int row = arow + p * 64;
            const float* wp = W + (size_t)(n0 + row) * K512 + k + ac8;
            const float4 w0 = *(const float4*)(wp);
            const float4 w1 = *(const float4*)(wp + 4);
            const float v[8] = { w0.x, w0.y, w0.z, w0.w, w1.x, w1.y, w1.z, w1.w };
            __align__(16) __nv_bfloat16 hi[8], lo[8];
            #pragma unroll
            for (int i = 0; i < 8; i++) {
                hi[i] = __float2bfloat16(v[i]);
                lo[i] = __float2bfloat16(v[i] - __bfloat162float(hi[i]));
            }
            *(uint4*)(sm + OFF_BHI + row * ROWB + ac8 * 2) = *(const uint4*)hi;
            *(uint4*)(sm + OFF_BLO + row * ROWB + ac8 * 2) = *(const uint4*)lo;
        }
        __syncthreads();

        // ---- mma phase ----
        #pragma unroll
        for (int ks = 0; ks < 2; ks++) {
            const int kb = (ks * 16 + c2) * 2;   // byte offset of k pair
            uint32_t ah[2][4], al[2][4], bh[4][2], bl[4][2];
            #pragma unroll
            for (int mf = 0; mf < 2; mf++) {
                const char* bh_ = sm + OFF_AHI + (wm + mf * 16 + r8) * ROWB;
                const char* bl_ = sm + OFF_ALO + (wm + mf * 16 + r8) * ROWB;
                ah[mf][0] = *(const uint32_t*)(bh_ + kb);
                ah[mf][1] = *(const uint32_t*)(bh_ + 8 * ROWB + kb);
                ah[mf][2] = *(const uint32_t*)(bh_ + kb + 16);
                ah[mf][3] = *(const uint32_t*)(bh_ + 8 * ROWB + kb + 16);
                al[mf][0] = *(const uint32_t*)(bl_ + kb);
                al[mf][1] = *(const uint32_t*)(bl_ + 8 * ROWB + kb);
                al[mf][2] = *(const uint32_t*)(bl_ + kb + 16);
                al[mf][3] = *(const uint32_t*)(bl_ + 8 * ROWB + kb + 16);
            }
            #pragma unroll
            for (int nf = 0; nf < 4; nf++) {
                const char* hb = sm + OFF_BHI + (wn + nf * 8 + r8) * ROWB;
                const char* lb = sm + OFF_BLO + (wn + nf * 8 + r8) * ROWB;
                bh[nf][0] = *(const uint32_t*)(hb + kb);
                bh[nf][1] = *(const uint32_t*)(hb + kb + 16);
                bl[nf][0] = *(const uint32_t*)(lb + kb);
                bl[nf][1] = *(const uint32_t*)(lb + kb + 16);
            }
            #pragma unroll
            for (int mf = 0; mf < 2; mf++)
                #pragma unroll
                for (int nf = 0; nf < 4; nf++) {
                    mma16816(acc[mf][nf], ah[mf], bh[nf]);   // hi*hi
                    mma16816(acc[mf][nf], al[mf], bh[nf]);   // lo*hi
                    mma16816(acc[mf][nf], ah[mf], bl[nf]);   // hi*lo
                }
        }
        __syncthreads();
    }

    // Epilogue: acc + bias -> C (fp32). C frag rows r8 / r8+8, cols c2, c2+1.
    #pragma unroll
    for (int mf = 0; mf < 2; mf++) {
        #pragma unroll
        for (int hh = 0; hh < 2; hh++) {
            const int m = m0 + wm + mf * 16 + hh * 8 + r8;
            float* crow = C + (size_t)m * G3 + n0 + wn;
            #pragma unroll
            for (int nf = 0; nf < 4; nf++) {
                const int n = nf * 8 + c2;
                float2 v;
                v.x = acc[mf][nf][hh * 2 + 0] + __ldg(&bias[n0 + wn + n]);
                v.y = acc[mf][nf][hh * 2 + 1] + __ldg(&bias[n0 + wn + n + 1]);
                *(float2*)(crow + n) = v;
            }
        }
    }
}

// ---- GEMM wrappers (operands are the same fp32 arrays round 2 used) ----
__global__ void __launch_bounds__(256) k_gi1_mma(const float* __restrict__ x,
                                                 const float* __restrict__ Wih1,
                                                 const float* __restrict__ bias) {
    gemm_core(x + blockIdx.z, XW, Wih1, bias, g_GI1 + (size_t)blockIdx.z * B * G3);
}
__global__ void __launch_bounds__(256) k_gh1_mma(const float* __restrict__ Whh1,
                                                 const float* __restrict__ bias) {
    gemm_core(g_h1, H, Whh1, bias, g_GH1);
}
__global__ void __launch_bounds__(256) k_g2_mma(const float* __restrict__ Wih2,
                                                const float* __restrict__ bih2,
                                                const float* __restrict__ Whh2,
                                                const float* __restrict__ bhh2) {
    if (blockIdx.z == 0) gemm_core(g_h1, H, Wih2, bih2, g_GI2);
    else                 gemm_core(g_h2, H, Whh2, bhh2, g_GH2);
}

// ---- pointwise GRU gate updates (exact round-2 passing code) ----
__device__ __forceinline__ float sigmoidf_(float v) { return 1.0f / (1.0f + expf(-v)); }

__global__ void k_gate1(int t)
{
    const int idx = blockIdx.x * blockDim.x + threadIdx.x;   // < B*H
    const int b = idx >> 9;
    const int j = idx & (H - 1);
    const float* gi = g_GI1 + (size_t)t * B * G3 + (size_t)b * G3;
    const float* gh = g_GH1 + (size_t)b * G3;
    const float r = sigmoidf_(gi[j]         + gh[j]);
    const float z = sigmoidf_(gi[H + j]     + gh[H + j]);
    const float n = tanhf    (gi[2 * H + j] + r * gh[2 * H + j]);
    const float h = g_h1[idx];
    g_h1[idx] = (1.0f - z) * n + z * h;
}

__global__ void k_gate2(int t)
{
    const int idx = blockIdx.x * blockDim.x + threadIdx.x;   // < B*H
    const int b = idx >> 9;
    const int j = idx & (H - 1);
    const float* gi = g_GI2 + (size_t)b * G3;
    const float* gh = g_GH2 + (size_t)b * G3;
    const float r = sigmoidf_(gi[j]         + gh[j]);
    const float z = sigmoidf_(gi[H + j]     + gh[H + j]);
    const float n = tanhf    (gi[2 * H + j] + r * gh[2 * H + j]);
    const float h = g_h2[idx];
    const float hn = (1.0f - z) * n + z * h;
    g_h2[idx] = hn;
    g_H2A[(size_t)t * B * H + idx] = hn;
}

// ---- FC head over the whole h2 history ----
__global__ void k_y(const float* __restrict__ Wfc, const float* __restrict__ bfc,
                    float* __restrict__ out)
{
    const int w    = (blockIdx.x * blockDim.x + threadIdx.x) >> 5;
    const int lane = threadIdx.x & 31;
    const int b = w >> 6;
    const int t = w & (L - 1);
    const float* h2 = g_H2A + ((size_t)t * B + b) * H;
    float acc = 0.0f;
    #pragma unroll 4
    for (int j = lane; j < H; j += 32) acc += h2[j] * Wfc[j];
    #pragma unroll
    for (int o = 16; o; o >>= 1) acc += __shfl_xor_sync(0xffffffffu, acc, o);
    if (lane == 0) out[b * L + t] = acc + bfc[0];
}

// ---- init / finalize ----
__global__ void k_init(const float* __restrict__ h1i, const float* __restrict__ h2i)
{
    const int i = blockIdx.x * blockDim.x + threadIdx.x;
    g_h1[i] = h1i[i];
    g_h2[i] = h2i[i];
}

__global__ void k_fin(float* __restrict__ out)
{
    const int i = blockIdx.x * blockDim.x + threadIdx.x;
    out[B * L + i]         = g_h1[i];
    out[B * L + B * H + i] = g_h2[i];
}

// ---------------------------------------------------------------
extern "C" void kernel_launch(void* const* d_in, const int* in_sizes, int n_in,
                              void* d_out, int out_size)
{
    (void)in_sizes; (void)n_in; (void)out_size;
    const float* x    = (const float*)d_in[0];
    const float* h1i  = (const float*)d_in[1];
    const float* h2i  = (const float*)d_in[2];
    const float* Wih1 = (const float*)d_in[3];
    const float* Whh1 = (const float*)d_in[4];
    const float* bih1 = (const float*)d_in[5];
    const float* bhh1 = (const float*)d_in[6];
    const float* Wih2 = (const float*)d_in[7];
    const float* Whh2 = (const float*)d_in[8];
    const float* bih2 = (const float*)d_in[9];
    const float* bhh2 = (const float*)d_in[10];
    const float* Wfc  = (const float*)d_in[11];
    const float* bfc  = (const float*)d_in[12];
    float* out = (float*)d_out;

    k_init<<<(B * H) / 256, 256>>>(h1i, h2i);

    // Hoisted input-side GEMM for all L steps (windows read in-place from x).
    k_gi1_mma<<<dim3(G3 / TN, B / TM, L), 256, SMEM_DYN>>>(x, Wih1, bih1);

    for (int t = 0; t < L; t++) {
        k_gh1_mma<<<dim3(G3 / TN, B / TM, 1), 256, SMEM_DYN>>>(Whh1, bhh1);
        k_gate1<<<(B * H) / 256, 256>>>(t);
        k_g2_mma<<<dim3(G3 / TN, B / TM, 2), 256, SMEM_DYN>>>(Wih2, bih2, Whh2, bhh2);
        k_gate2<<<(B * H) / 256, 256>>>(t);
    }

    k_y  <<<(B * L * 32) / 256, 256>>>(Wfc, bfc, out);
    k_fin<<<(B * H) / 256, 256>>>(out);
}